// round 14
// baseline (speedup 1.0000x reference)
#include <cuda_runtime.h>
#include <math.h>

#define MAXN 131072
#define TPB 256
#define ETPB 128
#define EGRID 1184

typedef unsigned long long u64;

// ---------------- device scratch ----------------
__device__ __align__(256) float  g_S[MAXN * 16];
__device__ float  g_deg[MAXN];
__device__ __align__(256) float  g_u[MAXN * 16];
__device__ __align__(256) float4 g_nA[MAXN];   // coords.xyz, curv0
__device__ __align__(256) float4 g_nB[MAXN];   // normals.xyz, curv1
__device__ double g_est[32];
__device__ double g_nst[32];
__device__ float  g_eac[32];
__device__ float  g_nac[32];
__device__ int    g_idx64;

// ---------------- f32x2 helpers ----------------
__device__ __forceinline__ u64 dup2(float x) {
    u64 r; asm("mov.b64 %0, {%1, %1};" : "=l"(r) : "f"(x)); return r;
}
__device__ __forceinline__ void upk2(u64 a, float& lo, float& hi) {
    asm("mov.b64 {%0, %1}, %2;" : "=f"(lo), "=f"(hi) : "l"(a));
}
__device__ __forceinline__ u64 fma2(u64 a, u64 b, u64 c) {
    u64 d; asm("fma.rn.f32x2 %0, %1, %2, %3;" : "=l"(d) : "l"(a), "l"(b), "l"(c)); return d;
}
__device__ __forceinline__ u64 mul2(u64 a, u64 b) {
    u64 d; asm("mul.rn.f32x2 %0, %1, %2;" : "=l"(d) : "l"(a), "l"(b)); return d;
}
__device__ __forceinline__ float tanh_ap(float x) {
    float r; asm("tanh.approx.f32 %0, %1;" : "=f"(r) : "f"(x)); return r;
}
// doubled tanh-form GELU: returns g' = x*(1+tanh(u)) = 2*gelu(x).
// The 0.5 is folded into the NEXT layer's weights (W2/2, W3/2).
__device__ __forceinline__ void gelu2x(u64 x, u64 K1, u64 K3, float& o0, float& o1) {
    u64 p = mul2(x, x);
    u64 q = fma2(p, K3, K1);      // K1 + K3*x^2
    u64 u = mul2(x, q);           // x*(K1 + K3*x^2)
    float u0, u1; upk2(u, u0, u1);
    float t0 = tanh_ap(u0), t1 = tanh_ap(u1);
    float x0, x1; upk2(x, x0, x1);
    o0 = fmaf(x0, t0, x0);        // x*(1+tanh)
    o1 = fmaf(x1, t1, x1);
}

__device__ __forceinline__ float warp_sum(float v) {
#pragma unroll
    for (int o = 16; o > 0; o >>= 1) v += __shfl_down_sync(0xffffffffu, v, o);
    return v;
}
__device__ __forceinline__ void red_add_v4(float* addr, float a, float b, float c, float d) {
    asm volatile("red.global.add.v4.f32 [%0], {%1,%2,%3,%4};"
                 :: "l"(addr), "f"(a), "f"(b), "f"(c), "f"(d) : "memory");
}

// ---------------- kernels ----------------
// fused zero + pack: tid range covers N*4 (float4-zero g_S) and N (deg + pack)
__global__ void prep_kernel(const float* __restrict__ coords,
                            const float* __restrict__ normals,
                            const float* __restrict__ curv, int N) {
    int tid = blockIdx.x * blockDim.x + threadIdx.x;
    int tot4 = N * 4;
    if (tid < tot4) ((float4*)g_S)[tid] = make_float4(0.f, 0.f, 0.f, 0.f);
    if (tid < N) {
        g_deg[tid] = 0.0f;
        g_nA[tid] = make_float4(coords[3*tid], coords[3*tid+1], coords[3*tid+2], curv[4*tid]);
        g_nB[tid] = make_float4(normals[3*tid], normals[3*tid+1], normals[3*tid+2], curv[4*tid+1]);
    }
    if (tid < 32) { g_est[tid] = 0.0; g_nst[tid] = 0.0; }
}

__global__ void probe_kernel(const void* __restrict__ eidx, int N) {
    if (threadIdx.x == 0 && blockIdx.x == 0) {
        const long long* q = (const long long*)eidx;
        int ok = 1;
#pragma unroll 1
        for (int i = 0; i < 64; i++) {
            long long v = q[i];
            if (v < 0 || v >= (long long)N) ok = 0;
        }
        g_idx64 = ok;
    }
}

__global__ void dummy_kernel() {}   // aligns edge_kernel to ncu launch slot

__device__ __forceinline__ void edge_features(
    const float4& Ar, const float4& Br, const float4& Ac, const float4& Bc, float* f)
{
    float dx = Ac.x - Ar.x, dy = Ac.y - Ar.y, dz = Ac.z - Ar.z;
    float ndot = Br.x * Bc.x + Br.y * Bc.y + Br.z * Bc.z;
    float dn = sqrtf(dx*dx + dy*dy + dz*dz) + 1e-8f;
    float invd = 1.0f / dn;
    float lo = -1.0f + 1e-8f, hi = 1.0f - 1e-8f;
    float cr = fminf(fmaxf((Br.x*dx + Br.y*dy + Br.z*dz) * invd, lo), hi);
    float cc = fminf(fmaxf((Bc.x*dx + Bc.y*dy + Bc.z*dz) * invd, lo), hi);
    f[0]=dx; f[1]=dy; f[2]=dz; f[3]=ndot; f[4]=cr; f[5]=cc;
    f[6]=Ac.w - Ar.w; f[7]=Bc.w - Br.w;
}

__global__ __launch_bounds__(ETPB) void edge_kernel(
    const void* __restrict__ eidx, long long E,
    const float* __restrict__ W1, const float* __restrict__ b1,
    const float* __restrict__ W2, const float* __restrict__ b2,
    const float* __restrict__ W3, const float* __restrict__ b3)
{
    // W1 interleaved into output-pair-major: entry (jp,k) = (W1[k][2jp], W1[k][2jp+1])
    __shared__ ulonglong2 W1p[32 * 4];   // [jp][kv], kv covers k=2kv,2kv+1
    __shared__ u64        b1p[32];
    __shared__ ulonglong2 W2p[64 * 8];   // natural row-major, PRE-SCALED by 0.5
    __shared__ u64        b2p[16];
    __shared__ ulonglong2 W3p[32 * 4];   // natural row-major, PRE-SCALED by 0.5
    __shared__ u64        b3p[8];
    __shared__ float      sred[16];

    {
        float* w1f = (float*)W1p;
        for (int t = threadIdx.x; t < 512; t += ETPB) {
            int k = t >> 6, j = t & 63;         // W1[k,j]
            int jp = j >> 1, h = j & 1;
            w1f[(jp * 8 + k) * 2 + h] = W1[t];
        }
        float* w2f = (float*)W2p;
        for (int t = threadIdx.x; t < 2048; t += ETPB) w2f[t] = 0.5f * W2[t];
        float* w3f = (float*)W3p;
        for (int t = threadIdx.x; t < 512;  t += ETPB) w3f[t] = 0.5f * W3[t];
        float* b1f = (float*)b1p;
        for (int t = threadIdx.x; t < 64; t += ETPB) b1f[t] = b1[t];
        float* b2f = (float*)b2p;
        for (int t = threadIdx.x; t < 32; t += ETPB) b2f[t] = b2[t];
        float* b3f = (float*)b3p;
        for (int t = threadIdx.x; t < 16; t += ETPB) b3f[t] = b3[t];
        if (threadIdx.x < 16) sred[threadIdx.x] = 0.0f;
    }
    __syncthreads();

    const int use64 = g_idx64;
    const int*       e32 = (const int*)eidx;
    const long long* e64 = (const long long*)eidx;

    const u64 K1 = dup2(0.7978845608028654f);
    const u64 K3 = dup2(0.035677408136300125f);

    u64 s1p[8];
#pragma unroll
    for (int i = 0; i < 8; i++) s1p[i] = 0ull;

    const long long stride = (long long)gridDim.x * ETPB * 2;
    for (long long e = ((long long)blockIdx.x * ETPB + threadIdx.x) * 2; e < E; e += stride) {
        bool dual = (e + 1 < E);
        int r0, c0, r1, c1;
        if (use64) {
            if (dual) {
                longlong2 rr = *(const longlong2*)&e64[e];
                longlong2 cc2 = *(const longlong2*)&e64[E + e];
                r0 = (int)rr.x; r1 = (int)rr.y;
                c0 = (int)cc2.x; c1 = (int)cc2.y;
            } else {
                r0 = r1 = (int)e64[e]; c0 = c1 = (int)e64[E + e];
            }
        } else {
            r0 = e32[e];  c0 = e32[E + e];
            r1 = dual ? e32[e + 1] : r0;
            c1 = dual ? e32[E + e + 1] : c0;
        }

        float4 Ar0 = __ldg(&g_nA[r0]), Br0 = __ldg(&g_nB[r0]);
        float4 Ac0 = __ldg(&g_nA[c0]), Bc0 = __ldg(&g_nB[c0]);
        float4 Ar1 = __ldg(&g_nA[r1]), Br1 = __ldg(&g_nB[r1]);
        float4 Ac1 = __ldg(&g_nA[c1]), Bc1 = __ldg(&g_nB[c1]);

        float f0[8], f1[8];
        edge_features(Ar0, Br0, Ac0, Bc0, f0);
        edge_features(Ar1, Br1, Ac1, Bc1, f1);

        // h2 accumulators: packed over adjacent outputs, per edge
        u64 h2a[16], h2b[16];
#pragma unroll
        for (int p = 0; p < 16; p++) { h2a[p] = b2p[p]; h2b[p] = h2a[p]; }

        // ---- L1 (packed over output pairs) -> gelu' -> L2 (W2/2) rank-1 updates ----
#pragma unroll 2
        for (int jp = 0; jp < 32; jp++) {
            u64 acc0 = b1p[jp], acc1 = acc0;
#pragma unroll
            for (int kv = 0; kv < 4; kv++) {
                ulonglong2 w = W1p[jp * 4 + kv];
                acc0 = fma2(dup2(f0[2*kv]),   w.x, acc0);
                acc0 = fma2(dup2(f0[2*kv+1]), w.y, acc0);
                acc1 = fma2(dup2(f1[2*kv]),   w.x, acc1);
                acc1 = fma2(dup2(f1[2*kv+1]), w.y, acc1);
            }
            float a00, a01, a10, a11;
            gelu2x(acc0, K1, K3, a00, a01);
            gelu2x(acc1, K1, K3, a10, a11);
            u64 d00 = dup2(a00), d01 = dup2(a01);
            u64 d10 = dup2(a10), d11 = dup2(a11);
            {
                const ulonglong2* w = &W2p[(2 * jp) * 8];
#pragma unroll
                for (int q = 0; q < 8; q++) {
                    ulonglong2 wv = w[q];
                    h2a[2*q]   = fma2(d00, wv.x, h2a[2*q]);
                    h2a[2*q+1] = fma2(d00, wv.y, h2a[2*q+1]);
                    h2b[2*q]   = fma2(d10, wv.x, h2b[2*q]);
                    h2b[2*q+1] = fma2(d10, wv.y, h2b[2*q+1]);
                }
            }
            {
                const ulonglong2* w = &W2p[(2 * jp + 1) * 8];
#pragma unroll
                for (int q = 0; q < 8; q++) {
                    ulonglong2 wv = w[q];
                    h2a[2*q]   = fma2(d01, wv.x, h2a[2*q]);
                    h2a[2*q+1] = fma2(d01, wv.y, h2a[2*q+1]);
                    h2b[2*q]   = fma2(d11, wv.x, h2b[2*q]);
                    h2b[2*q+1] = fma2(d11, wv.y, h2b[2*q+1]);
                }
            }
        }

        // ---- gelu'(h2) -> L3 (W3/2) ----
        u64 efa[8], efb[8];
#pragma unroll
        for (int p = 0; p < 8; p++) { efa[p] = b3p[p]; efb[p] = efa[p]; }
#pragma unroll 2
        for (int jp = 0; jp < 16; jp++) {
            float g00, g01, g10, g11;
            gelu2x(h2a[jp], K1, K3, g00, g01);
            gelu2x(h2b[jp], K1, K3, g10, g11);
            u64 d00 = dup2(g00), d01 = dup2(g01);
            u64 d10 = dup2(g10), d11 = dup2(g11);
            {
                const ulonglong2* w = &W3p[(2 * jp) * 4];
#pragma unroll
                for (int q = 0; q < 4; q++) {
                    ulonglong2 wv = w[q];
                    efa[2*q]   = fma2(d00, wv.x, efa[2*q]);
                    efa[2*q+1] = fma2(d00, wv.y, efa[2*q+1]);
                    efb[2*q]   = fma2(d10, wv.x, efb[2*q]);
                    efb[2*q+1] = fma2(d10, wv.y, efb[2*q+1]);
                }
            }
            {
                const ulonglong2* w = &W3p[(2 * jp + 1) * 4];
#pragma unroll
                for (int q = 0; q < 4; q++) {
                    ulonglong2 wv = w[q];
                    efa[2*q]   = fma2(d01, wv.x, efa[2*q]);
                    efa[2*q+1] = fma2(d01, wv.y, efa[2*q+1]);
                    efb[2*q]   = fma2(d11, wv.x, efb[2*q]);
                    efb[2*q+1] = fma2(d11, wv.y, efb[2*q+1]);
                }
            }
        }

        // ---- scatter + stats ----
        {
            float v[16];
#pragma unroll
            for (int p = 0; p < 8; p++) upk2(efa[p], v[2*p], v[2*p+1]);
            float* Sr = &g_S[(size_t)r0 * 16];
            float* Sc = &g_S[(size_t)c0 * 16];
#pragma unroll
            for (int q = 0; q < 4; q++) {
                red_add_v4(Sr + 4*q, v[4*q], v[4*q+1], v[4*q+2], v[4*q+3]);
                red_add_v4(Sc + 4*q, v[4*q], v[4*q+1], v[4*q+2], v[4*q+3]);
            }
            atomicAdd(&g_deg[r0], 1.0f);
            atomicAdd(&g_deg[c0], 1.0f);
#pragma unroll
            for (int p = 0; p < 8; p++) s1p[p] = fma2(efa[p], efa[p], s1p[p]);
        }
        if (dual) {
            float v[16];
#pragma unroll
            for (int p = 0; p < 8; p++) upk2(efb[p], v[2*p], v[2*p+1]);
            float* Sr = &g_S[(size_t)r1 * 16];
            float* Sc = &g_S[(size_t)c1 * 16];
#pragma unroll
            for (int q = 0; q < 4; q++) {
                red_add_v4(Sr + 4*q, v[4*q], v[4*q+1], v[4*q+2], v[4*q+3]);
                red_add_v4(Sc + 4*q, v[4*q], v[4*q+1], v[4*q+2], v[4*q+3]);
            }
            atomicAdd(&g_deg[r1], 1.0f);
            atomicAdd(&g_deg[c1], 1.0f);
#pragma unroll
            for (int p = 0; p < 8; p++) s1p[p] = fma2(efb[p], efb[p], s1p[p]);
        }
    }

    float s1[16];
#pragma unroll
    for (int p = 0; p < 8; p++) upk2(s1p[p], s1[2*p], s1[2*p+1]);
    int lane = threadIdx.x & 31;
#pragma unroll
    for (int i = 0; i < 16; i++) {
        float b = warp_sum(s1[i]);
        if (lane == 0) atomicAdd(&sred[i], b);
    }
    __syncthreads();
    if (threadIdx.x < 16) atomicAdd(&g_est[16 + threadIdx.x], (double)sred[threadIdx.x]);
}

// sum of g_S -> g_est[0:16) scaled by 0.5 (sum over edges of ef)
__global__ void sumS_kernel(int N) {
    float acc[4] = {0.f, 0.f, 0.f, 0.f};
    int tot4 = N * 4;
    int stride = gridDim.x * blockDim.x;
    int t0 = blockIdx.x * blockDim.x + threadIdx.x;
    const float4* S4 = (const float4*)g_S;
#pragma unroll 4
    for (int i = t0; i < tot4; i += stride) {
        float4 v = S4[i];
        acc[0] += v.x; acc[1] += v.y; acc[2] += v.z; acc[3] += v.w;
    }
#pragma unroll
    for (int k = 0; k < 4; k++) {
#pragma unroll
        for (int o = 16; o >= 4; o >>= 1) acc[k] += __shfl_down_sync(0xffffffffu, acc[k], o);
    }
    int lane = threadIdx.x & 31;
    if (lane < 4) {
        int base = (t0 & 3) * 4;
#pragma unroll
        for (int k = 0; k < 4; k++)
            atomicAdd(&g_est[base + k], 0.5 * (double)acc[k]);
    }
}

__global__ void fin_edge_kernel(const float* __restrict__ gamma,
                                const float* __restrict__ beta, long long E) {
    int i = threadIdx.x;
    if (i < 16) {
        double invE = 1.0 / (double)E;
        double mean = g_est[i] * invE;
        double var = g_est[16 + i] * invE - mean * mean;
        if (var < 0.0) var = 0.0;
        float a = gamma[i] * rsqrtf((float)var + 1e-5f);
        g_eac[i] = a;
        g_eac[16 + i] = beta[i] - (float)mean * a;
    }
}

__global__ __launch_bounds__(TPB) void node_kernel(
    const float* __restrict__ Wp, const float* __restrict__ bp, int N)
{
    __shared__ float Wps[256];
    __shared__ float bps[16];
    __shared__ float sred[32];
    if (threadIdx.x < 256) Wps[threadIdx.x] = Wp[threadIdx.x];
    if (threadIdx.x < 16)  bps[threadIdx.x] = bp[threadIdx.x];
    if (threadIdx.x < 32)  sred[threadIdx.x] = 0.0f;
    __syncthreads();

    int n = blockIdx.x * blockDim.x + threadIdx.x;
    float s0[16], s1[16];
#pragma unroll
    for (int i = 0; i < 16; i++) { s0[i] = 0.0f; s1[i] = 0.0f; }

    if (n < N) {
        float deg = g_deg[n];
        float invd = 1.0f / fmaxf(deg, 1.0f);
        float t[16];
#pragma unroll
        for (int i = 0; i < 16; i++)
            t[i] = (g_eac[i] * g_S[(size_t)n * 16 + i] + deg * g_eac[16 + i]) * invd;
        float u[16];
#pragma unroll
        for (int i = 0; i < 16; i++) u[i] = bps[i];
#pragma unroll
        for (int j = 0; j < 16; j++) {
#pragma unroll
            for (int i = 0; i < 16; i++) u[i] = fmaf(t[j], Wps[j * 16 + i], u[i]);
        }
#pragma unroll
        for (int i = 0; i < 16; i++) {
            g_u[(size_t)n * 16 + i] = u[i];
            s0[i] = u[i];
            s1[i] = u[i] * u[i];
        }
    }

    int lane = threadIdx.x & 31;
#pragma unroll
    for (int i = 0; i < 16; i++) {
        float a = warp_sum(s0[i]);
        float b = warp_sum(s1[i]);
        if (lane == 0) {
            atomicAdd(&sred[i], a);
            atomicAdd(&sred[16 + i], b);
        }
    }
    __syncthreads();
    if (threadIdx.x < 32) atomicAdd(&g_nst[threadIdx.x], (double)sred[threadIdx.x]);
}

__global__ void fin_node_kernel(const float* __restrict__ gamma,
                                const float* __restrict__ beta, int N) {
    int i = threadIdx.x;
    if (i < 16) {
        double invN = 1.0 / (double)N;
        double mean = g_nst[i] * invN;
        double var = g_nst[16 + i] * invN - mean * mean;
        if (var < 0.0) var = 0.0;
        float a = gamma[i] * rsqrtf((float)var + 1e-5f);
        g_nac[i] = a;
        g_nac[16 + i] = beta[i] - (float)mean * a;
    }
}

__global__ void final_kernel(float* __restrict__ out, int N) {
    int idx4 = blockIdx.x * blockDim.x + threadIdx.x;
    int tot4 = N * 4;
    if (idx4 < tot4) {
        int base = (idx4 * 4) & 15;
        const float4* u4 = (const float4*)g_u;
        float4 v = u4[idx4];
        float4 r;
        r.x = g_nac[base + 0] * v.x + g_nac[16 + base + 0];
        r.y = g_nac[base + 1] * v.y + g_nac[16 + base + 1];
        r.z = g_nac[base + 2] * v.z + g_nac[16 + base + 2];
        r.w = g_nac[base + 3] * v.w + g_nac[16 + base + 3];
        ((float4*)out)[idx4] = r;
    }
}

// ---------------- launch ----------------
extern "C" void kernel_launch(void* const* d_in, const int* in_sizes, int n_in,
                              void* d_out, int out_size)
{
    const float* coords  = (const float*)d_in[0];
    const float* normals = (const float*)d_in[1];
    const float* curv    = (const float*)d_in[2];
    const void*  eidx    = d_in[3];
    const float* W1 = (const float*)d_in[4];
    const float* b1 = (const float*)d_in[5];
    const float* W2 = (const float*)d_in[6];
    const float* b2 = (const float*)d_in[7];
    const float* W3 = (const float*)d_in[8];
    const float* b3 = (const float*)d_in[9];
    const float* bn_e_gamma = (const float*)d_in[10];
    const float* bn_e_beta  = (const float*)d_in[11];
    const float* Wp = (const float*)d_in[12];
    const float* bp = (const float*)d_in[13];
    const float* bn_n_gamma = (const float*)d_in[14];
    const float* bn_n_beta  = (const float*)d_in[15];

    int N = in_sizes[0] / 3;
    long long E = (long long)(in_sizes[3] / 2);
    float* out = (float*)d_out;

    prep_kernel<<<(N * 4 + TPB - 1) / TPB, TPB>>>(coords, normals, curv, N);
    probe_kernel<<<1, 32>>>(eidx, N);
    dummy_kernel<<<1, 32>>>();
    edge_kernel<<<EGRID, ETPB>>>(eidx, E, W1, b1, W2, b2, W3, b3);
    sumS_kernel<<<592, 256>>>(N);
    fin_edge_kernel<<<1, 32>>>(bn_e_gamma, bn_e_beta, E);
    node_kernel<<<(N + TPB - 1) / TPB, TPB>>>(Wp, bp, N);
    fin_node_kernel<<<1, 32>>>(bn_n_gamma, bn_n_beta, N);
    final_kernel<<<(N * 4 + TPB - 1) / TPB, TPB>>>(out, N);
}

// round 15
// speedup vs baseline: 1.1431x; 1.1431x over previous
#include <cuda_runtime.h>
#include <math.h>

#define MAXN 131072
#define TPB 256
#define ETPB 128
#define EGRID 1184

typedef unsigned long long u64;

// ---------------- device scratch ----------------
__device__ __align__(256) float  g_S[MAXN * 16];
__device__ float  g_deg[MAXN];
__device__ __align__(256) float  g_u[MAXN * 16];
__device__ __align__(256) float4 g_nA[MAXN];   // coords.xyz, curv0
__device__ __align__(256) float4 g_nB[MAXN];   // normals.xyz, curv1
__device__ double g_est[32];
__device__ double g_nst[32];
__device__ float  g_eac[32];
__device__ float  g_nac[32];
__device__ int    g_idx64;

// ---------------- f32x2 helpers ----------------
__device__ __forceinline__ u64 dup2(float x) {
    u64 r; asm("mov.b64 %0, {%1, %1};" : "=l"(r) : "f"(x)); return r;
}
__device__ __forceinline__ void upk2(u64 a, float& lo, float& hi) {
    asm("mov.b64 {%0, %1}, %2;" : "=f"(lo), "=f"(hi) : "l"(a));
}
__device__ __forceinline__ u64 fma2(u64 a, u64 b, u64 c) {
    u64 d; asm("fma.rn.f32x2 %0, %1, %2, %3;" : "=l"(d) : "l"(a), "l"(b), "l"(c)); return d;
}
__device__ __forceinline__ u64 mul2(u64 a, u64 b) {
    u64 d; asm("mul.rn.f32x2 %0, %1, %2;" : "=l"(d) : "l"(a), "l"(b)); return d;
}
__device__ __forceinline__ float tanh_ap(float x) {
    float r; asm("tanh.approx.f32 %0, %1;" : "=f"(r) : "f"(x)); return r;
}
// doubled tanh-form GELU: returns g' = x*(1+tanh(u)) = 2*gelu(x).
// The 0.5 is folded into the NEXT layer's weights (W2/2, W3/2).
__device__ __forceinline__ void gelu2x(u64 x, u64 K1, u64 K3, float& o0, float& o1) {
    u64 p = mul2(x, x);
    u64 q = fma2(p, K3, K1);      // K1 + K3*x^2
    u64 u = mul2(x, q);           // x*(K1 + K3*x^2)
    float u0, u1; upk2(u, u0, u1);
    float t0 = tanh_ap(u0), t1 = tanh_ap(u1);
    float x0, x1; upk2(x, x0, x1);
    o0 = fmaf(x0, t0, x0);        // x*(1+tanh)
    o1 = fmaf(x1, t1, x1);
}

__device__ __forceinline__ float warp_sum(float v) {
#pragma unroll
    for (int o = 16; o > 0; o >>= 1) v += __shfl_down_sync(0xffffffffu, v, o);
    return v;
}
__device__ __forceinline__ void red_add_v4(float* addr, float a, float b, float c, float d) {
    asm volatile("red.global.add.v4.f32 [%0], {%1,%2,%3,%4};"
                 :: "l"(addr), "f"(a), "f"(b), "f"(c), "f"(d) : "memory");
}

// ---------------- kernels ----------------
// fused zero + pack: tid range covers N*4 (float4-zero g_S) and N (deg + pack)
__global__ void prep_kernel(const float* __restrict__ coords,
                            const float* __restrict__ normals,
                            const float* __restrict__ curv, int N) {
    int tid = blockIdx.x * blockDim.x + threadIdx.x;
    int tot4 = N * 4;
    if (tid < tot4) ((float4*)g_S)[tid] = make_float4(0.f, 0.f, 0.f, 0.f);
    if (tid < N) {
        g_deg[tid] = 0.0f;
        g_nA[tid] = make_float4(coords[3*tid], coords[3*tid+1], coords[3*tid+2], curv[4*tid]);
        g_nB[tid] = make_float4(normals[3*tid], normals[3*tid+1], normals[3*tid+2], curv[4*tid+1]);
    }
    if (tid < 32) { g_est[tid] = 0.0; g_nst[tid] = 0.0; }
}

__global__ void probe_kernel(const void* __restrict__ eidx, int N) {
    if (threadIdx.x == 0 && blockIdx.x == 0) {
        const long long* q = (const long long*)eidx;
        int ok = 1;
#pragma unroll 1
        for (int i = 0; i < 64; i++) {
            long long v = q[i];
            if (v < 0 || v >= (long long)N) ok = 0;
        }
        g_idx64 = ok;
    }
}

__device__ __forceinline__ void edge_features(
    const float4& Ar, const float4& Br, const float4& Ac, const float4& Bc, float* f)
{
    float dx = Ac.x - Ar.x, dy = Ac.y - Ar.y, dz = Ac.z - Ar.z;
    float ndot = Br.x * Bc.x + Br.y * Bc.y + Br.z * Bc.z;
    float dn = sqrtf(dx*dx + dy*dy + dz*dz) + 1e-8f;
    float invd = 1.0f / dn;
    float lo = -1.0f + 1e-8f, hi = 1.0f - 1e-8f;
    float cr = fminf(fmaxf((Br.x*dx + Br.y*dy + Br.z*dz) * invd, lo), hi);
    float cc = fminf(fmaxf((Bc.x*dx + Bc.y*dy + Bc.z*dz) * invd, lo), hi);
    f[0]=dx; f[1]=dy; f[2]=dz; f[3]=ndot; f[4]=cr; f[5]=cc;
    f[6]=Ac.w - Ar.w; f[7]=Bc.w - Br.w;
}

__global__ __launch_bounds__(ETPB) void edge_kernel(
    const void* __restrict__ eidx, long long E,
    const float* __restrict__ W1, const float* __restrict__ b1,
    const float* __restrict__ W2, const float* __restrict__ b2,
    const float* __restrict__ W3, const float* __restrict__ b3)
{
    // W1 interleaved into output-pair-major: entry (jp,k) = (W1[k][2jp], W1[k][2jp+1])
    __shared__ ulonglong2 W1p[32 * 4];   // [jp][kv], kv covers k=2kv,2kv+1
    __shared__ u64        b1p[32];
    __shared__ ulonglong2 W2p[64 * 8];   // natural row-major, PRE-SCALED by 0.5
    __shared__ u64        b2p[16];
    __shared__ ulonglong2 W3p[32 * 4];   // natural row-major, PRE-SCALED by 0.5
    __shared__ u64        b3p[8];
    __shared__ float      sred[16];

    {
        float* w1f = (float*)W1p;
        for (int t = threadIdx.x; t < 512; t += ETPB) {
            int k = t >> 6, j = t & 63;         // W1[k,j]
            int jp = j >> 1, h = j & 1;
            w1f[(jp * 8 + k) * 2 + h] = W1[t];
        }
        float* w2f = (float*)W2p;
        for (int t = threadIdx.x; t < 2048; t += ETPB) w2f[t] = 0.5f * W2[t];
        float* w3f = (float*)W3p;
        for (int t = threadIdx.x; t < 512;  t += ETPB) w3f[t] = 0.5f * W3[t];
        float* b1f = (float*)b1p;
        for (int t = threadIdx.x; t < 64; t += ETPB) b1f[t] = b1[t];
        float* b2f = (float*)b2p;
        for (int t = threadIdx.x; t < 32; t += ETPB) b2f[t] = b2[t];
        float* b3f = (float*)b3p;
        for (int t = threadIdx.x; t < 16; t += ETPB) b3f[t] = b3[t];
        if (threadIdx.x < 16) sred[threadIdx.x] = 0.0f;
    }
    __syncthreads();

    const int use64 = g_idx64;
    const int*       e32 = (const int*)eidx;
    const long long* e64 = (const long long*)eidx;

    const u64 K1 = dup2(0.7978845608028654f);
    const u64 K3 = dup2(0.035677408136300125f);

    u64 s1p[8];
#pragma unroll
    for (int i = 0; i < 8; i++) s1p[i] = 0ull;

    const long long stride = (long long)gridDim.x * ETPB * 2;
    for (long long e = ((long long)blockIdx.x * ETPB + threadIdx.x) * 2; e < E; e += stride) {
        bool dual = (e + 1 < E);
        int r0, c0, r1, c1;
        if (use64) {
            if (dual) {
                longlong2 rr = *(const longlong2*)&e64[e];
                longlong2 cc2 = *(const longlong2*)&e64[E + e];
                r0 = (int)rr.x; r1 = (int)rr.y;
                c0 = (int)cc2.x; c1 = (int)cc2.y;
            } else {
                r0 = r1 = (int)e64[e]; c0 = c1 = (int)e64[E + e];
            }
        } else {
            r0 = e32[e];  c0 = e32[E + e];
            r1 = dual ? e32[e + 1] : r0;
            c1 = dual ? e32[E + e + 1] : c0;
        }

        float4 Ar0 = __ldg(&g_nA[r0]), Br0 = __ldg(&g_nB[r0]);
        float4 Ac0 = __ldg(&g_nA[c0]), Bc0 = __ldg(&g_nB[c0]);
        float4 Ar1 = __ldg(&g_nA[r1]), Br1 = __ldg(&g_nB[r1]);
        float4 Ac1 = __ldg(&g_nA[c1]), Bc1 = __ldg(&g_nB[c1]);

        float f0[8], f1[8];
        edge_features(Ar0, Br0, Ac0, Bc0, f0);
        edge_features(Ar1, Br1, Ac1, Bc1, f1);

        // h2 accumulators: packed over adjacent outputs, per edge
        u64 h2a[16], h2b[16];
#pragma unroll
        for (int p = 0; p < 16; p++) { h2a[p] = b2p[p]; h2b[p] = h2a[p]; }

        // ---- L1 (packed over output pairs) -> gelu' -> L2 (W2/2) rank-1 updates ----
#pragma unroll 2
        for (int jp = 0; jp < 32; jp++) {
            u64 acc0 = b1p[jp], acc1 = acc0;
#pragma unroll
            for (int kv = 0; kv < 4; kv++) {
                ulonglong2 w = W1p[jp * 4 + kv];
                acc0 = fma2(dup2(f0[2*kv]),   w.x, acc0);
                acc0 = fma2(dup2(f0[2*kv+1]), w.y, acc0);
                acc1 = fma2(dup2(f1[2*kv]),   w.x, acc1);
                acc1 = fma2(dup2(f1[2*kv+1]), w.y, acc1);
            }
            float a00, a01, a10, a11;
            gelu2x(acc0, K1, K3, a00, a01);
            gelu2x(acc1, K1, K3, a10, a11);
            u64 d00 = dup2(a00), d01 = dup2(a01);
            u64 d10 = dup2(a10), d11 = dup2(a11);
            {
                const ulonglong2* w = &W2p[(2 * jp) * 8];
#pragma unroll
                for (int q = 0; q < 8; q++) {
                    ulonglong2 wv = w[q];
                    h2a[2*q]   = fma2(d00, wv.x, h2a[2*q]);
                    h2a[2*q+1] = fma2(d00, wv.y, h2a[2*q+1]);
                    h2b[2*q]   = fma2(d10, wv.x, h2b[2*q]);
                    h2b[2*q+1] = fma2(d10, wv.y, h2b[2*q+1]);
                }
            }
            {
                const ulonglong2* w = &W2p[(2 * jp + 1) * 8];
#pragma unroll
                for (int q = 0; q < 8; q++) {
                    ulonglong2 wv = w[q];
                    h2a[2*q]   = fma2(d01, wv.x, h2a[2*q]);
                    h2a[2*q+1] = fma2(d01, wv.y, h2a[2*q+1]);
                    h2b[2*q]   = fma2(d11, wv.x, h2b[2*q]);
                    h2b[2*q+1] = fma2(d11, wv.y, h2b[2*q+1]);
                }
            }
        }

        // ---- gelu'(h2) -> L3 (W3/2) ----
        u64 efa[8], efb[8];
#pragma unroll
        for (int p = 0; p < 8; p++) { efa[p] = b3p[p]; efb[p] = efa[p]; }
#pragma unroll 2
        for (int jp = 0; jp < 16; jp++) {
            float g00, g01, g10, g11;
            gelu2x(h2a[jp], K1, K3, g00, g01);
            gelu2x(h2b[jp], K1, K3, g10, g11);
            u64 d00 = dup2(g00), d01 = dup2(g01);
            u64 d10 = dup2(g10), d11 = dup2(g11);
            {
                const ulonglong2* w = &W3p[(2 * jp) * 4];
#pragma unroll
                for (int q = 0; q < 4; q++) {
                    ulonglong2 wv = w[q];
                    efa[2*q]   = fma2(d00, wv.x, efa[2*q]);
                    efa[2*q+1] = fma2(d00, wv.y, efa[2*q+1]);
                    efb[2*q]   = fma2(d10, wv.x, efb[2*q]);
                    efb[2*q+1] = fma2(d10, wv.y, efb[2*q+1]);
                }
            }
            {
                const ulonglong2* w = &W3p[(2 * jp + 1) * 4];
#pragma unroll
                for (int q = 0; q < 4; q++) {
                    ulonglong2 wv = w[q];
                    efa[2*q]   = fma2(d01, wv.x, efa[2*q]);
                    efa[2*q+1] = fma2(d01, wv.y, efa[2*q+1]);
                    efb[2*q]   = fma2(d11, wv.x, efb[2*q]);
                    efb[2*q+1] = fma2(d11, wv.y, efb[2*q+1]);
                }
            }
        }

        // ---- scatter + stats ----
        {
            float v[16];
#pragma unroll
            for (int p = 0; p < 8; p++) upk2(efa[p], v[2*p], v[2*p+1]);
            float* Sr = &g_S[(size_t)r0 * 16];
            float* Sc = &g_S[(size_t)c0 * 16];
#pragma unroll
            for (int q = 0; q < 4; q++) {
                red_add_v4(Sr + 4*q, v[4*q], v[4*q+1], v[4*q+2], v[4*q+3]);
                red_add_v4(Sc + 4*q, v[4*q], v[4*q+1], v[4*q+2], v[4*q+3]);
            }
            atomicAdd(&g_deg[r0], 1.0f);
            atomicAdd(&g_deg[c0], 1.0f);
#pragma unroll
            for (int p = 0; p < 8; p++) s1p[p] = fma2(efa[p], efa[p], s1p[p]);
        }
        if (dual) {
            float v[16];
#pragma unroll
            for (int p = 0; p < 8; p++) upk2(efb[p], v[2*p], v[2*p+1]);
            float* Sr = &g_S[(size_t)r1 * 16];
            float* Sc = &g_S[(size_t)c1 * 16];
#pragma unroll
            for (int q = 0; q < 4; q++) {
                red_add_v4(Sr + 4*q, v[4*q], v[4*q+1], v[4*q+2], v[4*q+3]);
                red_add_v4(Sc + 4*q, v[4*q], v[4*q+1], v[4*q+2], v[4*q+3]);
            }
            atomicAdd(&g_deg[r1], 1.0f);
            atomicAdd(&g_deg[c1], 1.0f);
#pragma unroll
            for (int p = 0; p < 8; p++) s1p[p] = fma2(efb[p], efb[p], s1p[p]);
        }
    }

    float s1[16];
#pragma unroll
    for (int p = 0; p < 8; p++) upk2(s1p[p], s1[2*p], s1[2*p+1]);
    int lane = threadIdx.x & 31;
#pragma unroll
    for (int i = 0; i < 16; i++) {
        float b = warp_sum(s1[i]);
        if (lane == 0) atomicAdd(&sred[i], b);
    }
    __syncthreads();
    if (threadIdx.x < 16) atomicAdd(&g_est[16 + threadIdx.x], (double)sred[threadIdx.x]);
}

// sum of g_S -> g_est[0:16) scaled by 0.5 (sum over edges of ef).
// Per-block shared aggregation -> only 16 global double atomics per block.
__global__ void sumS_kernel(int N) {
    __shared__ float sb[16];
    if (threadIdx.x < 16) sb[threadIdx.x] = 0.0f;
    __syncthreads();

    float acc[4] = {0.f, 0.f, 0.f, 0.f};
    int tot4 = N * 4;
    int stride = gridDim.x * blockDim.x;     // multiple of 4
    int t0 = blockIdx.x * blockDim.x + threadIdx.x;
    const float4* S4 = (const float4*)g_S;
    for (int i = t0; i < tot4; i += stride) {
        float4 v = S4[i];
        acc[0] += v.x; acc[1] += v.y; acc[2] += v.z; acc[3] += v.w;
    }
#pragma unroll
    for (int k = 0; k < 4; k++) {
#pragma unroll
        for (int o = 16; o >= 4; o >>= 1) acc[k] += __shfl_down_sync(0xffffffffu, acc[k], o);
    }
    int lane = threadIdx.x & 31;             // lanes 0..3 hold class lane (= t0&3)
    if (lane < 4) {
#pragma unroll
        for (int k = 0; k < 4; k++) atomicAdd(&sb[lane * 4 + k], acc[k]);
    }
    __syncthreads();
    if (threadIdx.x < 16) atomicAdd(&g_est[threadIdx.x], 0.5 * (double)sb[threadIdx.x]);
}

__global__ void fin_edge_kernel(const float* __restrict__ gamma,
                                const float* __restrict__ beta, long long E) {
    int i = threadIdx.x;
    if (i < 16) {
        double invE = 1.0 / (double)E;
        double mean = g_est[i] * invE;
        double var = g_est[16 + i] * invE - mean * mean;
        if (var < 0.0) var = 0.0;
        float a = gamma[i] * rsqrtf((float)var + 1e-5f);
        g_eac[i] = a;
        g_eac[16 + i] = beta[i] - (float)mean * a;
    }
}

__global__ __launch_bounds__(TPB) void node_kernel(
    const float* __restrict__ Wp, const float* __restrict__ bp, int N)
{
    __shared__ float Wps[256];
    __shared__ float bps[16];
    __shared__ float sred[32];
    if (threadIdx.x < 256) Wps[threadIdx.x] = Wp[threadIdx.x];
    if (threadIdx.x < 16)  bps[threadIdx.x] = bp[threadIdx.x];
    if (threadIdx.x < 32)  sred[threadIdx.x] = 0.0f;
    __syncthreads();

    int n = blockIdx.x * blockDim.x + threadIdx.x;
    float s0[16], s1[16];
#pragma unroll
    for (int i = 0; i < 16; i++) { s0[i] = 0.0f; s1[i] = 0.0f; }

    if (n < N) {
        float deg = g_deg[n];
        float invd = 1.0f / fmaxf(deg, 1.0f);
        float t[16];
#pragma unroll
        for (int i = 0; i < 16; i++)
            t[i] = (g_eac[i] * g_S[(size_t)n * 16 + i] + deg * g_eac[16 + i]) * invd;
        float u[16];
#pragma unroll
        for (int i = 0; i < 16; i++) u[i] = bps[i];
#pragma unroll
        for (int j = 0; j < 16; j++) {
#pragma unroll
            for (int i = 0; i < 16; i++) u[i] = fmaf(t[j], Wps[j * 16 + i], u[i]);
        }
#pragma unroll
        for (int i = 0; i < 16; i++) {
            g_u[(size_t)n * 16 + i] = u[i];
            s0[i] = u[i];
            s1[i] = u[i] * u[i];
        }
    }

    int lane = threadIdx.x & 31;
#pragma unroll
    for (int i = 0; i < 16; i++) {
        float a = warp_sum(s0[i]);
        float b = warp_sum(s1[i]);
        if (lane == 0) {
            atomicAdd(&sred[i], a);
            atomicAdd(&sred[16 + i], b);
        }
    }
    __syncthreads();
    if (threadIdx.x < 32) atomicAdd(&g_nst[threadIdx.x], (double)sred[threadIdx.x]);
}

__global__ void fin_node_kernel(const float* __restrict__ gamma,
                                const float* __restrict__ beta, int N) {
    int i = threadIdx.x;
    if (i < 16) {
        double invN = 1.0 / (double)N;
        double mean = g_nst[i] * invN;
        double var = g_nst[16 + i] * invN - mean * mean;
        if (var < 0.0) var = 0.0;
        float a = gamma[i] * rsqrtf((float)var + 1e-5f);
        g_nac[i] = a;
        g_nac[16 + i] = beta[i] - (float)mean * a;
    }
}

__global__ void final_kernel(float* __restrict__ out, int N) {
    int idx4 = blockIdx.x * blockDim.x + threadIdx.x;
    int tot4 = N * 4;
    if (idx4 < tot4) {
        int base = (idx4 * 4) & 15;
        const float4* u4 = (const float4*)g_u;
        float4 v = u4[idx4];
        float4 r;
        r.x = g_nac[base + 0] * v.x + g_nac[16 + base + 0];
        r.y = g_nac[base + 1] * v.y + g_nac[16 + base + 1];
        r.z = g_nac[base + 2] * v.z + g_nac[16 + base + 2];
        r.w = g_nac[base + 3] * v.w + g_nac[16 + base + 3];
        ((float4*)out)[idx4] = r;
    }
}

// ---------------- launch ----------------
extern "C" void kernel_launch(void* const* d_in, const int* in_sizes, int n_in,
                              void* d_out, int out_size)
{
    const float* coords  = (const float*)d_in[0];
    const float* normals = (const float*)d_in[1];
    const float* curv    = (const float*)d_in[2];
    const void*  eidx    = d_in[3];
    const float* W1 = (const float*)d_in[4];
    const float* b1 = (const float*)d_in[5];
    const float* W2 = (const float*)d_in[6];
    const float* b2 = (const float*)d_in[7];
    const float* W3 = (const float*)d_in[8];
    const float* b3 = (const float*)d_in[9];
    const float* bn_e_gamma = (const float*)d_in[10];
    const float* bn_e_beta  = (const float*)d_in[11];
    const float* Wp = (const float*)d_in[12];
    const float* bp = (const float*)d_in[13];
    const float* bn_n_gamma = (const float*)d_in[14];
    const float* bn_n_beta  = (const float*)d_in[15];

    int N = in_sizes[0] / 3;
    long long E = (long long)(in_sizes[3] / 2);
    float* out = (float*)d_out;

    prep_kernel<<<(N * 4 + TPB - 1) / TPB, TPB>>>(coords, normals, curv, N);
    probe_kernel<<<1, 32>>>(eidx, N);
    edge_kernel<<<EGRID, ETPB>>>(eidx, E, W1, b1, W2, b2, W3, b3);
    sumS_kernel<<<592, TPB>>>(N);
    fin_edge_kernel<<<1, 32>>>(bn_e_gamma, bn_e_beta, E);
    node_kernel<<<(N + TPB - 1) / TPB, TPB>>>(Wp, bp, N);
    fin_node_kernel<<<1, 32>>>(bn_n_gamma, bn_n_beta, N);
    final_kernel<<<(N * 4 + TPB - 1) / TPB, TPB>>>(out, N);
}

// round 16
// speedup vs baseline: 1.1568x; 1.0120x over previous
#include <cuda_runtime.h>
#include <math.h>

#define MAXN 131072
#define TPB 256
#define ETPB 128
#define EGRID 1184

typedef unsigned long long u64;

// ---------------- device scratch ----------------
__device__ __align__(256) float  g_S[MAXN * 16];
__device__ float  g_deg[MAXN];
__device__ __align__(256) float  g_u[MAXN * 16];
__device__ __align__(256) float4 g_nA[MAXN];   // coords.xyz, curv0
__device__ __align__(256) float4 g_nB[MAXN];   // normals.xyz, curv1
__device__ double g_est[32];
__device__ double g_nst[32];
__device__ int    g_idx64;

// ---------------- f32x2 helpers ----------------
__device__ __forceinline__ u64 dup2(float x) {
    u64 r; asm("mov.b64 %0, {%1, %1};" : "=l"(r) : "f"(x)); return r;
}
__device__ __forceinline__ void upk2(u64 a, float& lo, float& hi) {
    asm("mov.b64 {%0, %1}, %2;" : "=f"(lo), "=f"(hi) : "l"(a));
}
__device__ __forceinline__ u64 fma2(u64 a, u64 b, u64 c) {
    u64 d; asm("fma.rn.f32x2 %0, %1, %2, %3;" : "=l"(d) : "l"(a), "l"(b), "l"(c)); return d;
}
__device__ __forceinline__ u64 mul2(u64 a, u64 b) {
    u64 d; asm("mul.rn.f32x2 %0, %1, %2;" : "=l"(d) : "l"(a), "l"(b)); return d;
}
__device__ __forceinline__ float tanh_ap(float x) {
    float r; asm("tanh.approx.f32 %0, %1;" : "=f"(r) : "f"(x)); return r;
}
// doubled tanh-form GELU: returns g' = x*(1+tanh(u)) = 2*gelu(x).
// The 0.5 is folded into the NEXT layer's weights (W2/2, W3/2).
__device__ __forceinline__ void gelu2x(u64 x, u64 K1, u64 K3, float& o0, float& o1) {
    u64 p = mul2(x, x);
    u64 q = fma2(p, K3, K1);      // K1 + K3*x^2
    u64 u = mul2(x, q);           // x*(K1 + K3*x^2)
    float u0, u1; upk2(u, u0, u1);
    float t0 = tanh_ap(u0), t1 = tanh_ap(u1);
    float x0, x1; upk2(x, x0, x1);
    o0 = fmaf(x0, t0, x0);        // x*(1+tanh)
    o1 = fmaf(x1, t1, x1);
}

__device__ __forceinline__ float warp_sum(float v) {
#pragma unroll
    for (int o = 16; o > 0; o >>= 1) v += __shfl_down_sync(0xffffffffu, v, o);
    return v;
}
__device__ __forceinline__ void red_add_v4(float* addr, float a, float b, float c, float d) {
    asm volatile("red.global.add.v4.f32 [%0], {%1,%2,%3,%4};"
                 :: "l"(addr), "f"(a), "f"(b), "f"(c), "f"(d) : "memory");
}

// ---------------- kernels ----------------
// fused zero + pack + probe
__global__ void prep_kernel(const float* __restrict__ coords,
                            const float* __restrict__ normals,
                            const float* __restrict__ curv,
                            const void* __restrict__ eidx, int N) {
    int tid = blockIdx.x * blockDim.x + threadIdx.x;
    int tot4 = N * 4;
    if (tid < tot4) ((float4*)g_S)[tid] = make_float4(0.f, 0.f, 0.f, 0.f);
    if (tid < N) {
        g_deg[tid] = 0.0f;
        g_nA[tid] = make_float4(coords[3*tid], coords[3*tid+1], coords[3*tid+2], curv[4*tid]);
        g_nB[tid] = make_float4(normals[3*tid], normals[3*tid+1], normals[3*tid+2], curv[4*tid+1]);
    }
    if (tid < 32) { g_est[tid] = 0.0; g_nst[tid] = 0.0; }
    if (tid == 0) {
        const long long* q = (const long long*)eidx;
        int ok = 1;
#pragma unroll 1
        for (int i = 0; i < 64; i++) {
            long long v = q[i];
            if (v < 0 || v >= (long long)N) ok = 0;
        }
        g_idx64 = ok;
    }
}

__device__ __forceinline__ void edge_features(
    const float4& Ar, const float4& Br, const float4& Ac, const float4& Bc, float* f)
{
    float dx = Ac.x - Ar.x, dy = Ac.y - Ar.y, dz = Ac.z - Ar.z;
    float ndot = Br.x * Bc.x + Br.y * Bc.y + Br.z * Bc.z;
    float dn = sqrtf(dx*dx + dy*dy + dz*dz) + 1e-8f;
    float invd = 1.0f / dn;
    float lo = -1.0f + 1e-8f, hi = 1.0f - 1e-8f;
    float cr = fminf(fmaxf((Br.x*dx + Br.y*dy + Br.z*dz) * invd, lo), hi);
    float cc = fminf(fmaxf((Bc.x*dx + Bc.y*dy + Bc.z*dz) * invd, lo), hi);
    f[0]=dx; f[1]=dy; f[2]=dz; f[3]=ndot; f[4]=cr; f[5]=cc;
    f[6]=Ac.w - Ar.w; f[7]=Bc.w - Br.w;
}

__global__ __launch_bounds__(ETPB) void edge_kernel(
    const void* __restrict__ eidx, long long E,
    const float* __restrict__ W1, const float* __restrict__ b1,
    const float* __restrict__ W2, const float* __restrict__ b2,
    const float* __restrict__ W3, const float* __restrict__ b3)
{
    // W1 interleaved into output-pair-major: entry (jp,k) = (W1[k][2jp], W1[k][2jp+1])
    __shared__ ulonglong2 W1p[32 * 4];   // [jp][kv], kv covers k=2kv,2kv+1
    __shared__ u64        b1p[32];
    __shared__ ulonglong2 W2p[64 * 8];   // natural row-major, PRE-SCALED by 0.5
    __shared__ u64        b2p[16];
    __shared__ ulonglong2 W3p[32 * 4];   // natural row-major, PRE-SCALED by 0.5
    __shared__ u64        b3p[8];
    __shared__ float      sred[16];

    {
        float* w1f = (float*)W1p;
        for (int t = threadIdx.x; t < 512; t += ETPB) {
            int k = t >> 6, j = t & 63;         // W1[k,j]
            int jp = j >> 1, h = j & 1;
            w1f[(jp * 8 + k) * 2 + h] = W1[t];
        }
        float* w2f = (float*)W2p;
        for (int t = threadIdx.x; t < 2048; t += ETPB) w2f[t] = 0.5f * W2[t];
        float* w3f = (float*)W3p;
        for (int t = threadIdx.x; t < 512;  t += ETPB) w3f[t] = 0.5f * W3[t];
        float* b1f = (float*)b1p;
        for (int t = threadIdx.x; t < 64; t += ETPB) b1f[t] = b1[t];
        float* b2f = (float*)b2p;
        for (int t = threadIdx.x; t < 32; t += ETPB) b2f[t] = b2[t];
        float* b3f = (float*)b3p;
        for (int t = threadIdx.x; t < 16; t += ETPB) b3f[t] = b3[t];
        if (threadIdx.x < 16) sred[threadIdx.x] = 0.0f;
    }
    __syncthreads();

    const int use64 = g_idx64;
    const int*       e32 = (const int*)eidx;
    const long long* e64 = (const long long*)eidx;

    const u64 K1 = dup2(0.7978845608028654f);
    const u64 K3 = dup2(0.035677408136300125f);

    u64 s1p[8];
#pragma unroll
    for (int i = 0; i < 8; i++) s1p[i] = 0ull;

    const long long stride = (long long)gridDim.x * ETPB * 2;
    for (long long e = ((long long)blockIdx.x * ETPB + threadIdx.x) * 2; e < E; e += stride) {
        bool dual = (e + 1 < E);
        int r0, c0, r1, c1;
        if (use64) {
            if (dual) {
                longlong2 rr = *(const longlong2*)&e64[e];
                longlong2 cc2 = *(const longlong2*)&e64[E + e];
                r0 = (int)rr.x; r1 = (int)rr.y;
                c0 = (int)cc2.x; c1 = (int)cc2.y;
            } else {
                r0 = r1 = (int)e64[e]; c0 = c1 = (int)e64[E + e];
            }
        } else {
            r0 = e32[e];  c0 = e32[E + e];
            r1 = dual ? e32[e + 1] : r0;
            c1 = dual ? e32[E + e + 1] : c0;
        }

        float4 Ar0 = __ldg(&g_nA[r0]), Br0 = __ldg(&g_nB[r0]);
        float4 Ac0 = __ldg(&g_nA[c0]), Bc0 = __ldg(&g_nB[c0]);
        float4 Ar1 = __ldg(&g_nA[r1]), Br1 = __ldg(&g_nB[r1]);
        float4 Ac1 = __ldg(&g_nA[c1]), Bc1 = __ldg(&g_nB[c1]);

        float f0[8], f1[8];
        edge_features(Ar0, Br0, Ac0, Bc0, f0);
        edge_features(Ar1, Br1, Ac1, Bc1, f1);

        // h2 accumulators: packed over adjacent outputs, per edge
        u64 h2a[16], h2b[16];
#pragma unroll
        for (int p = 0; p < 16; p++) { h2a[p] = b2p[p]; h2b[p] = h2a[p]; }

        // ---- L1 (packed over output pairs) -> gelu' -> L2 (W2/2) rank-1 updates ----
#pragma unroll 2
        for (int jp = 0; jp < 32; jp++) {
            u64 acc0 = b1p[jp], acc1 = acc0;
#pragma unroll
            for (int kv = 0; kv < 4; kv++) {
                ulonglong2 w = W1p[jp * 4 + kv];
                acc0 = fma2(dup2(f0[2*kv]),   w.x, acc0);
                acc0 = fma2(dup2(f0[2*kv+1]), w.y, acc0);
                acc1 = fma2(dup2(f1[2*kv]),   w.x, acc1);
                acc1 = fma2(dup2(f1[2*kv+1]), w.y, acc1);
            }
            float a00, a01, a10, a11;
            gelu2x(acc0, K1, K3, a00, a01);
            gelu2x(acc1, K1, K3, a10, a11);
            u64 d00 = dup2(a00), d01 = dup2(a01);
            u64 d10 = dup2(a10), d11 = dup2(a11);
            {
                const ulonglong2* w = &W2p[(2 * jp) * 8];
#pragma unroll
                for (int q = 0; q < 8; q++) {
                    ulonglong2 wv = w[q];
                    h2a[2*q]   = fma2(d00, wv.x, h2a[2*q]);
                    h2a[2*q+1] = fma2(d00, wv.y, h2a[2*q+1]);
                    h2b[2*q]   = fma2(d10, wv.x, h2b[2*q]);
                    h2b[2*q+1] = fma2(d10, wv.y, h2b[2*q+1]);
                }
            }
            {
                const ulonglong2* w = &W2p[(2 * jp + 1) * 8];
#pragma unroll
                for (int q = 0; q < 8; q++) {
                    ulonglong2 wv = w[q];
                    h2a[2*q]   = fma2(d01, wv.x, h2a[2*q]);
                    h2a[2*q+1] = fma2(d01, wv.y, h2a[2*q+1]);
                    h2b[2*q]   = fma2(d11, wv.x, h2b[2*q]);
                    h2b[2*q+1] = fma2(d11, wv.y, h2b[2*q+1]);
                }
            }
        }

        // ---- gelu'(h2) -> L3 (W3/2) ----
        u64 efa[8], efb[8];
#pragma unroll
        for (int p = 0; p < 8; p++) { efa[p] = b3p[p]; efb[p] = efa[p]; }
#pragma unroll 2
        for (int jp = 0; jp < 16; jp++) {
            float g00, g01, g10, g11;
            gelu2x(h2a[jp], K1, K3, g00, g01);
            gelu2x(h2b[jp], K1, K3, g10, g11);
            u64 d00 = dup2(g00), d01 = dup2(g01);
            u64 d10 = dup2(g10), d11 = dup2(g11);
            {
                const ulonglong2* w = &W3p[(2 * jp) * 4];
#pragma unroll
                for (int q = 0; q < 4; q++) {
                    ulonglong2 wv = w[q];
                    efa[2*q]   = fma2(d00, wv.x, efa[2*q]);
                    efa[2*q+1] = fma2(d00, wv.y, efa[2*q+1]);
                    efb[2*q]   = fma2(d10, wv.x, efb[2*q]);
                    efb[2*q+1] = fma2(d10, wv.y, efb[2*q+1]);
                }
            }
            {
                const ulonglong2* w = &W3p[(2 * jp + 1) * 4];
#pragma unroll
                for (int q = 0; q < 4; q++) {
                    ulonglong2 wv = w[q];
                    efa[2*q]   = fma2(d01, wv.x, efa[2*q]);
                    efa[2*q+1] = fma2(d01, wv.y, efa[2*q+1]);
                    efb[2*q]   = fma2(d11, wv.x, efb[2*q]);
                    efb[2*q+1] = fma2(d11, wv.y, efb[2*q+1]);
                }
            }
        }

        // ---- scatter + stats ----
        {
            float v[16];
#pragma unroll
            for (int p = 0; p < 8; p++) upk2(efa[p], v[2*p], v[2*p+1]);
            float* Sr = &g_S[(size_t)r0 * 16];
            float* Sc = &g_S[(size_t)c0 * 16];
#pragma unroll
            for (int q = 0; q < 4; q++) {
                red_add_v4(Sr + 4*q, v[4*q], v[4*q+1], v[4*q+2], v[4*q+3]);
                red_add_v4(Sc + 4*q, v[4*q], v[4*q+1], v[4*q+2], v[4*q+3]);
            }
            atomicAdd(&g_deg[r0], 1.0f);
            atomicAdd(&g_deg[c0], 1.0f);
#pragma unroll
            for (int p = 0; p < 8; p++) s1p[p] = fma2(efa[p], efa[p], s1p[p]);
        }
        if (dual) {
            float v[16];
#pragma unroll
            for (int p = 0; p < 8; p++) upk2(efb[p], v[2*p], v[2*p+1]);
            float* Sr = &g_S[(size_t)r1 * 16];
            float* Sc = &g_S[(size_t)c1 * 16];
#pragma unroll
            for (int q = 0; q < 4; q++) {
                red_add_v4(Sr + 4*q, v[4*q], v[4*q+1], v[4*q+2], v[4*q+3]);
                red_add_v4(Sc + 4*q, v[4*q], v[4*q+1], v[4*q+2], v[4*q+3]);
            }
            atomicAdd(&g_deg[r1], 1.0f);
            atomicAdd(&g_deg[c1], 1.0f);
#pragma unroll
            for (int p = 0; p < 8; p++) s1p[p] = fma2(efb[p], efb[p], s1p[p]);
        }
    }

    float s1[16];
#pragma unroll
    for (int p = 0; p < 8; p++) upk2(s1p[p], s1[2*p], s1[2*p+1]);
    int lane = threadIdx.x & 31;
#pragma unroll
    for (int i = 0; i < 16; i++) {
        float b = warp_sum(s1[i]);
        if (lane == 0) atomicAdd(&sred[i], b);
    }
    __syncthreads();
    if (threadIdx.x < 16) atomicAdd(&g_est[16 + threadIdx.x], (double)sred[threadIdx.x]);
}

// sum of g_S -> g_est[0:16) scaled by 0.5; 4-way batched loads for MLP.
__global__ void sumS_kernel(int N) {
    __shared__ float sb[16];
    if (threadIdx.x < 16) sb[threadIdx.x] = 0.0f;
    __syncthreads();

    float acc[4] = {0.f, 0.f, 0.f, 0.f};
    int tot4 = N * 4;
    int stride = gridDim.x * blockDim.x;     // multiple of 4
    int t0 = blockIdx.x * blockDim.x + threadIdx.x;
    const float4* S4 = (const float4*)g_S;
    for (int i = t0; i < tot4; i += 4 * stride) {
        int i1 = i + stride, i2 = i + 2 * stride, i3 = i + 3 * stride;
        float4 v0 = S4[i];
        float4 v1 = (i1 < tot4) ? S4[i1] : make_float4(0.f,0.f,0.f,0.f);
        float4 v2 = (i2 < tot4) ? S4[i2] : make_float4(0.f,0.f,0.f,0.f);
        float4 v3 = (i3 < tot4) ? S4[i3] : make_float4(0.f,0.f,0.f,0.f);
        acc[0] += v0.x + v1.x + v2.x + v3.x;
        acc[1] += v0.y + v1.y + v2.y + v3.y;
        acc[2] += v0.z + v1.z + v2.z + v3.z;
        acc[3] += v0.w + v1.w + v2.w + v3.w;
    }
#pragma unroll
    for (int k = 0; k < 4; k++) {
#pragma unroll
        for (int o = 16; o >= 4; o >>= 1) acc[k] += __shfl_down_sync(0xffffffffu, acc[k], o);
    }
    int lane = threadIdx.x & 31;             // lanes 0..3 hold class lane (= t0&3)
    if (lane < 4) {
#pragma unroll
        for (int k = 0; k < 4; k++) atomicAdd(&sb[lane * 4 + k], acc[k]);
    }
    __syncthreads();
    if (threadIdx.x < 16) atomicAdd(&g_est[threadIdx.x], 0.5 * (double)sb[threadIdx.x]);
}

// node transform; edge-BN affine recomputed per block from g_est (folds fin_edge)
__global__ __launch_bounds__(TPB) void node_kernel(
    const float* __restrict__ Wp, const float* __restrict__ bp,
    const float* __restrict__ egamma, const float* __restrict__ ebeta,
    long long E, int N)
{
    __shared__ float Wps[256];
    __shared__ float bps[16];
    __shared__ float eac[32];
    __shared__ float sred[32];
    if (threadIdx.x < 256) Wps[threadIdx.x] = Wp[threadIdx.x];
    if (threadIdx.x < 16)  bps[threadIdx.x] = bp[threadIdx.x];
    if (threadIdx.x < 32)  sred[threadIdx.x] = 0.0f;
    if (threadIdx.x < 16) {
        int i = threadIdx.x;
        double invE = 1.0 / (double)E;
        double mean = g_est[i] * invE;
        double var = g_est[16 + i] * invE - mean * mean;
        if (var < 0.0) var = 0.0;
        float a = egamma[i] * rsqrtf((float)var + 1e-5f);
        eac[i] = a;
        eac[16 + i] = ebeta[i] - (float)mean * a;
    }
    __syncthreads();

    int n = blockIdx.x * blockDim.x + threadIdx.x;
    float s0[16], s1[16];
#pragma unroll
    for (int i = 0; i < 16; i++) { s0[i] = 0.0f; s1[i] = 0.0f; }

    if (n < N) {
        float deg = g_deg[n];
        float invd = 1.0f / fmaxf(deg, 1.0f);
        float t[16];
#pragma unroll
        for (int i = 0; i < 16; i++)
            t[i] = (eac[i] * g_S[(size_t)n * 16 + i] + deg * eac[16 + i]) * invd;
        float u[16];
#pragma unroll
        for (int i = 0; i < 16; i++) u[i] = bps[i];
#pragma unroll
        for (int j = 0; j < 16; j++) {
#pragma unroll
            for (int i = 0; i < 16; i++) u[i] = fmaf(t[j], Wps[j * 16 + i], u[i]);
        }
#pragma unroll
        for (int i = 0; i < 16; i++) {
            g_u[(size_t)n * 16 + i] = u[i];
            s0[i] = u[i];
            s1[i] = u[i] * u[i];
        }
    }

    int lane = threadIdx.x & 31;
#pragma unroll
    for (int i = 0; i < 16; i++) {
        float a = warp_sum(s0[i]);
        float b = warp_sum(s1[i]);
        if (lane == 0) {
            atomicAdd(&sred[i], a);
            atomicAdd(&sred[16 + i], b);
        }
    }
    __syncthreads();
    if (threadIdx.x < 32) atomicAdd(&g_nst[threadIdx.x], (double)sred[threadIdx.x]);
}

// final: node-BN affine recomputed per block from g_nst (folds fin_node)
__global__ void final_kernel(float* __restrict__ out,
                             const float* __restrict__ ngamma,
                             const float* __restrict__ nbeta, int N) {
    __shared__ float nac[32];
    if (threadIdx.x < 16) {
        int i = threadIdx.x;
        double invN = 1.0 / (double)N;
        double mean = g_nst[i] * invN;
        double var = g_nst[16 + i] * invN - mean * mean;
        if (var < 0.0) var = 0.0;
        float a = ngamma[i] * rsqrtf((float)var + 1e-5f);
        nac[i] = a;
        nac[16 + i] = nbeta[i] - (float)mean * a;
    }
    __syncthreads();

    int idx4 = blockIdx.x * blockDim.x + threadIdx.x;
    int tot4 = N * 4;
    if (idx4 < tot4) {
        int base = (idx4 * 4) & 15;
        const float4* u4 = (const float4*)g_u;
        float4 v = u4[idx4];
        float4 r;
        r.x = nac[base + 0] * v.x + nac[16 + base + 0];
        r.y = nac[base + 1] * v.y + nac[16 + base + 1];
        r.z = nac[base + 2] * v.z + nac[16 + base + 2];
        r.w = nac[base + 3] * v.w + nac[16 + base + 3];
        ((float4*)out)[idx4] = r;
    }
}

// ---------------- launch ----------------
extern "C" void kernel_launch(void* const* d_in, const int* in_sizes, int n_in,
                              void* d_out, int out_size)
{
    const float* coords  = (const float*)d_in[0];
    const float* normals = (const float*)d_in[1];
    const float* curv    = (const float*)d_in[2];
    const void*  eidx    = d_in[3];
    const float* W1 = (const float*)d_in[4];
    const float* b1 = (const float*)d_in[5];
    const float* W2 = (const float*)d_in[6];
    const float* b2 = (const float*)d_in[7];
    const float* W3 = (const float*)d_in[8];
    const float* b3 = (const float*)d_in[9];
    const float* bn_e_gamma = (const float*)d_in[10];
    const float* bn_e_beta  = (const float*)d_in[11];
    const float* Wp = (const float*)d_in[12];
    const float* bp = (const float*)d_in[13];
    const float* bn_n_gamma = (const float*)d_in[14];
    const float* bn_n_beta  = (const float*)d_in[15];

    int N = in_sizes[0] / 3;
    long long E = (long long)(in_sizes[3] / 2);
    float* out = (float*)d_out;

    prep_kernel<<<(N * 4 + TPB - 1) / TPB, TPB>>>(coords, normals, curv, eidx, N);
    edge_kernel<<<EGRID, ETPB>>>(eidx, E, W1, b1, W2, b2, W3, b3);
    sumS_kernel<<<592, TPB>>>(N);
    node_kernel<<<(N + TPB - 1) / TPB, TPB>>>(Wp, bp, bn_e_gamma, bn_e_beta, E, N);
    final_kernel<<<(N * 4 + TPB - 1) / TPB, TPB>>>(out, bn_n_gamma, bn_n_beta, N);
}

// round 17
// speedup vs baseline: 1.1571x; 1.0002x over previous
#include <cuda_runtime.h>
#include <math.h>

#define MAXN 131072
#define TPB 256
#define ETPB 128
#define EGRID 1184

typedef unsigned long long u64;

// ---------------- device scratch ----------------
__device__ __align__(256) float  g_S[MAXN * 16];
__device__ float  g_deg[MAXN];
__device__ __align__(256) float  g_u[MAXN * 16];
__device__ __align__(256) float4 g_nA[MAXN];   // coords.xyz, curv0
__device__ __align__(256) float4 g_nB[MAXN];   // normals.xyz, curv1
__device__ double g_est[32];
__device__ double g_nst[32];
__device__ int    g_idx64;

// ---------------- f32x2 helpers ----------------
__device__ __forceinline__ u64 dup2(float x) {
    u64 r; asm("mov.b64 %0, {%1, %1};" : "=l"(r) : "f"(x)); return r;
}
__device__ __forceinline__ void upk2(u64 a, float& lo, float& hi) {
    asm("mov.b64 {%0, %1}, %2;" : "=f"(lo), "=f"(hi) : "l"(a));
}
__device__ __forceinline__ u64 fma2(u64 a, u64 b, u64 c) {
    u64 d; asm("fma.rn.f32x2 %0, %1, %2, %3;" : "=l"(d) : "l"(a), "l"(b), "l"(c)); return d;
}
__device__ __forceinline__ u64 mul2(u64 a, u64 b) {
    u64 d; asm("mul.rn.f32x2 %0, %1, %2;" : "=l"(d) : "l"(a), "l"(b)); return d;
}
__device__ __forceinline__ float tanh_ap(float x) {
    float r; asm("tanh.approx.f32 %0, %1;" : "=f"(r) : "f"(x)); return r;
}
// doubled tanh-form GELU: returns g' = x*(1+tanh(u)) = 2*gelu(x).
// The 0.5 is folded into the NEXT layer's weights (W2/2, W3/2).
__device__ __forceinline__ void gelu2x(u64 x, u64 K1, u64 K3, float& o0, float& o1) {
    u64 p = mul2(x, x);
    u64 q = fma2(p, K3, K1);      // K1 + K3*x^2
    u64 u = mul2(x, q);           // x*(K1 + K3*x^2)
    float u0, u1; upk2(u, u0, u1);
    float t0 = tanh_ap(u0), t1 = tanh_ap(u1);
    float x0, x1; upk2(x, x0, x1);
    o0 = fmaf(x0, t0, x0);        // x*(1+tanh)
    o1 = fmaf(x1, t1, x1);
}

__device__ __forceinline__ float warp_sum(float v) {
#pragma unroll
    for (int o = 16; o > 0; o >>= 1) v += __shfl_down_sync(0xffffffffu, v, o);
    return v;
}
__device__ __forceinline__ void red_add_v4(float* addr, float a, float b, float c, float d) {
    asm volatile("red.global.add.v4.f32 [%0], {%1,%2,%3,%4};"
                 :: "l"(addr), "f"(a), "f"(b), "f"(c), "f"(d) : "memory");
}

// ---------------- kernels ----------------
// fused zero + pack + probe
__global__ void prep_kernel(const float* __restrict__ coords,
                            const float* __restrict__ normals,
                            const float* __restrict__ curv,
                            const void* __restrict__ eidx, int N) {
    int tid = blockIdx.x * blockDim.x + threadIdx.x;
    int tot4 = N * 4;
    if (tid < tot4) ((float4*)g_S)[tid] = make_float4(0.f, 0.f, 0.f, 0.f);
    if (tid < N) {
        g_deg[tid] = 0.0f;
        g_nA[tid] = make_float4(coords[3*tid], coords[3*tid+1], coords[3*tid+2], curv[4*tid]);
        g_nB[tid] = make_float4(normals[3*tid], normals[3*tid+1], normals[3*tid+2], curv[4*tid+1]);
    }
    if (tid < 32) { g_est[tid] = 0.0; g_nst[tid] = 0.0; }
    if (tid == 0) {
        const long long* q = (const long long*)eidx;
        int ok = 1;
#pragma unroll 1
        for (int i = 0; i < 64; i++) {
            long long v = q[i];
            if (v < 0 || v >= (long long)N) ok = 0;
        }
        g_idx64 = ok;
    }
}

__device__ __forceinline__ void edge_features(
    const float4& Ar, const float4& Br, const float4& Ac, const float4& Bc, float* f)
{
    float dx = Ac.x - Ar.x, dy = Ac.y - Ar.y, dz = Ac.z - Ar.z;
    float ndot = Br.x * Bc.x + Br.y * Bc.y + Br.z * Bc.z;
    float dn = sqrtf(dx*dx + dy*dy + dz*dz) + 1e-8f;
    float invd = 1.0f / dn;
    float lo = -1.0f + 1e-8f, hi = 1.0f - 1e-8f;
    float cr = fminf(fmaxf((Br.x*dx + Br.y*dy + Br.z*dz) * invd, lo), hi);
    float cc = fminf(fmaxf((Bc.x*dx + Bc.y*dy + Bc.z*dz) * invd, lo), hi);
    f[0]=dx; f[1]=dy; f[2]=dz; f[3]=ndot; f[4]=cr; f[5]=cc;
    f[6]=Ac.w - Ar.w; f[7]=Bc.w - Br.w;
}

__global__ __launch_bounds__(ETPB) void edge_kernel(
    const void* __restrict__ eidx, long long E,
    const float* __restrict__ W1, const float* __restrict__ b1,
    const float* __restrict__ W2, const float* __restrict__ b2,
    const float* __restrict__ W3, const float* __restrict__ b3)
{
    // W1 interleaved into output-pair-major: entry (jp,k) = (W1[k][2jp], W1[k][2jp+1])
    __shared__ ulonglong2 W1p[32 * 4];   // [jp][kv], kv covers k=2kv,2kv+1
    __shared__ u64        b1p[32];
    __shared__ ulonglong2 W2p[64 * 8];   // natural row-major, PRE-SCALED by 0.5
    __shared__ u64        b2p[16];
    __shared__ ulonglong2 W3p[32 * 4];   // natural row-major, PRE-SCALED by 0.5
    __shared__ u64        b3p[8];
    __shared__ float      sred[16];

    {
        float* w1f = (float*)W1p;
        for (int t = threadIdx.x; t < 512; t += ETPB) {
            int k = t >> 6, j = t & 63;         // W1[k,j]
            int jp = j >> 1, h = j & 1;
            w1f[(jp * 8 + k) * 2 + h] = W1[t];
        }
        float* w2f = (float*)W2p;
        for (int t = threadIdx.x; t < 2048; t += ETPB) w2f[t] = 0.5f * W2[t];
        float* w3f = (float*)W3p;
        for (int t = threadIdx.x; t < 512;  t += ETPB) w3f[t] = 0.5f * W3[t];
        float* b1f = (float*)b1p;
        for (int t = threadIdx.x; t < 64; t += ETPB) b1f[t] = b1[t];
        float* b2f = (float*)b2p;
        for (int t = threadIdx.x; t < 32; t += ETPB) b2f[t] = b2[t];
        float* b3f = (float*)b3p;
        for (int t = threadIdx.x; t < 16; t += ETPB) b3f[t] = b3[t];
        if (threadIdx.x < 16) sred[threadIdx.x] = 0.0f;
    }
    __syncthreads();

    const int use64 = g_idx64;
    const int*       e32 = (const int*)eidx;
    const long long* e64 = (const long long*)eidx;

    const u64 K1 = dup2(0.7978845608028654f);
    const u64 K3 = dup2(0.035677408136300125f);

    u64 s1p[8];
#pragma unroll
    for (int i = 0; i < 8; i++) s1p[i] = 0ull;

    const long long stride = (long long)gridDim.x * ETPB * 2;
    for (long long e = ((long long)blockIdx.x * ETPB + threadIdx.x) * 2; e < E; e += stride) {
        bool dual = (e + 1 < E);
        int r0, c0, r1, c1;
        if (use64) {
            if (dual) {
                longlong2 rr = *(const longlong2*)&e64[e];
                longlong2 cc2 = *(const longlong2*)&e64[E + e];
                r0 = (int)rr.x; r1 = (int)rr.y;
                c0 = (int)cc2.x; c1 = (int)cc2.y;
            } else {
                r0 = r1 = (int)e64[e]; c0 = c1 = (int)e64[E + e];
            }
        } else {
            r0 = e32[e];  c0 = e32[E + e];
            r1 = dual ? e32[e + 1] : r0;
            c1 = dual ? e32[E + e + 1] : c0;
        }

        float4 Ar0 = __ldg(&g_nA[r0]), Br0 = __ldg(&g_nB[r0]);
        float4 Ac0 = __ldg(&g_nA[c0]), Bc0 = __ldg(&g_nB[c0]);
        float4 Ar1 = __ldg(&g_nA[r1]), Br1 = __ldg(&g_nB[r1]);
        float4 Ac1 = __ldg(&g_nA[c1]), Bc1 = __ldg(&g_nB[c1]);

        float f0[8], f1[8];
        edge_features(Ar0, Br0, Ac0, Bc0, f0);
        edge_features(Ar1, Br1, Ac1, Bc1, f1);

        // h2 accumulators: packed over adjacent outputs, per edge
        u64 h2a[16], h2b[16];
#pragma unroll
        for (int p = 0; p < 16; p++) { h2a[p] = b2p[p]; h2b[p] = h2a[p]; }

        // ---- L1 (packed over output pairs) -> gelu' -> L2 (W2/2) rank-1 updates ----
#pragma unroll 2
        for (int jp = 0; jp < 32; jp++) {
            u64 acc0 = b1p[jp], acc1 = acc0;
#pragma unroll
            for (int kv = 0; kv < 4; kv++) {
                ulonglong2 w = W1p[jp * 4 + kv];
                acc0 = fma2(dup2(f0[2*kv]),   w.x, acc0);
                acc0 = fma2(dup2(f0[2*kv+1]), w.y, acc0);
                acc1 = fma2(dup2(f1[2*kv]),   w.x, acc1);
                acc1 = fma2(dup2(f1[2*kv+1]), w.y, acc1);
            }
            float a00, a01, a10, a11;
            gelu2x(acc0, K1, K3, a00, a01);
            gelu2x(acc1, K1, K3, a10, a11);
            u64 d00 = dup2(a00), d01 = dup2(a01);
            u64 d10 = dup2(a10), d11 = dup2(a11);
            {
                const ulonglong2* w = &W2p[(2 * jp) * 8];
#pragma unroll
                for (int q = 0; q < 8; q++) {
                    ulonglong2 wv = w[q];
                    h2a[2*q]   = fma2(d00, wv.x, h2a[2*q]);
                    h2a[2*q+1] = fma2(d00, wv.y, h2a[2*q+1]);
                    h2b[2*q]   = fma2(d10, wv.x, h2b[2*q]);
                    h2b[2*q+1] = fma2(d10, wv.y, h2b[2*q+1]);
                }
            }
            {
                const ulonglong2* w = &W2p[(2 * jp + 1) * 8];
#pragma unroll
                for (int q = 0; q < 8; q++) {
                    ulonglong2 wv = w[q];
                    h2a[2*q]   = fma2(d01, wv.x, h2a[2*q]);
                    h2a[2*q+1] = fma2(d01, wv.y, h2a[2*q+1]);
                    h2b[2*q]   = fma2(d11, wv.x, h2b[2*q]);
                    h2b[2*q+1] = fma2(d11, wv.y, h2b[2*q+1]);
                }
            }
        }

        // ---- gelu'(h2) -> L3 (W3/2) ----
        u64 efa[8], efb[8];
#pragma unroll
        for (int p = 0; p < 8; p++) { efa[p] = b3p[p]; efb[p] = efa[p]; }
#pragma unroll 2
        for (int jp = 0; jp < 16; jp++) {
            float g00, g01, g10, g11;
            gelu2x(h2a[jp], K1, K3, g00, g01);
            gelu2x(h2b[jp], K1, K3, g10, g11);
            u64 d00 = dup2(g00), d01 = dup2(g01);
            u64 d10 = dup2(g10), d11 = dup2(g11);
            {
                const ulonglong2* w = &W3p[(2 * jp) * 4];
#pragma unroll
                for (int q = 0; q < 4; q++) {
                    ulonglong2 wv = w[q];
                    efa[2*q]   = fma2(d00, wv.x, efa[2*q]);
                    efa[2*q+1] = fma2(d00, wv.y, efa[2*q+1]);
                    efb[2*q]   = fma2(d10, wv.x, efb[2*q]);
                    efb[2*q+1] = fma2(d10, wv.y, efb[2*q+1]);
                }
            }
            {
                const ulonglong2* w = &W3p[(2 * jp + 1) * 4];
#pragma unroll
                for (int q = 0; q < 4; q++) {
                    ulonglong2 wv = w[q];
                    efa[2*q]   = fma2(d01, wv.x, efa[2*q]);
                    efa[2*q+1] = fma2(d01, wv.y, efa[2*q+1]);
                    efb[2*q]   = fma2(d11, wv.x, efb[2*q]);
                    efb[2*q+1] = fma2(d11, wv.y, efb[2*q+1]);
                }
            }
        }

        // ---- scatter + stats ----
        {
            float v[16];
#pragma unroll
            for (int p = 0; p < 8; p++) upk2(efa[p], v[2*p], v[2*p+1]);
            float* Sr = &g_S[(size_t)r0 * 16];
            float* Sc = &g_S[(size_t)c0 * 16];
#pragma unroll
            for (int q = 0; q < 4; q++) {
                red_add_v4(Sr + 4*q, v[4*q], v[4*q+1], v[4*q+2], v[4*q+3]);
                red_add_v4(Sc + 4*q, v[4*q], v[4*q+1], v[4*q+2], v[4*q+3]);
            }
            atomicAdd(&g_deg[r0], 1.0f);
            atomicAdd(&g_deg[c0], 1.0f);
#pragma unroll
            for (int p = 0; p < 8; p++) s1p[p] = fma2(efa[p], efa[p], s1p[p]);
        }
        if (dual) {
            float v[16];
#pragma unroll
            for (int p = 0; p < 8; p++) upk2(efb[p], v[2*p], v[2*p+1]);
            float* Sr = &g_S[(size_t)r1 * 16];
            float* Sc = &g_S[(size_t)c1 * 16];
#pragma unroll
            for (int q = 0; q < 4; q++) {
                red_add_v4(Sr + 4*q, v[4*q], v[4*q+1], v[4*q+2], v[4*q+3]);
                red_add_v4(Sc + 4*q, v[4*q], v[4*q+1], v[4*q+2], v[4*q+3]);
            }
            atomicAdd(&g_deg[r1], 1.0f);
            atomicAdd(&g_deg[c1], 1.0f);
#pragma unroll
            for (int p = 0; p < 8; p++) s1p[p] = fma2(efb[p], efb[p], s1p[p]);
        }
    }

    float s1[16];
#pragma unroll
    for (int p = 0; p < 8; p++) upk2(s1p[p], s1[2*p], s1[2*p+1]);
    int lane = threadIdx.x & 31;
#pragma unroll
    for (int i = 0; i < 16; i++) {
        float b = warp_sum(s1[i]);
        if (lane == 0) atomicAdd(&sred[i], b);
    }
    __syncthreads();
    if (threadIdx.x < 16) atomicAdd(&g_est[16 + threadIdx.x], (double)sred[threadIdx.x]);
}

// sum of g_S -> g_est[0:16) scaled by 0.5; 4-way batched loads for MLP.
__global__ void sumS_kernel(int N) {
    __shared__ float sb[16];
    if (threadIdx.x < 16) sb[threadIdx.x] = 0.0f;
    __syncthreads();

    float acc[4] = {0.f, 0.f, 0.f, 0.f};
    int tot4 = N * 4;
    int stride = gridDim.x * blockDim.x;     // multiple of 4
    int t0 = blockIdx.x * blockDim.x + threadIdx.x;
    const float4* S4 = (const float4*)g_S;
    for (int i = t0; i < tot4; i += 4 * stride) {
        int i1 = i + stride, i2 = i + 2 * stride, i3 = i + 3 * stride;
        float4 v0 = S4[i];
        float4 v1 = (i1 < tot4) ? S4[i1] : make_float4(0.f,0.f,0.f,0.f);
        float4 v2 = (i2 < tot4) ? S4[i2] : make_float4(0.f,0.f,0.f,0.f);
        float4 v3 = (i3 < tot4) ? S4[i3] : make_float4(0.f,0.f,0.f,0.f);
        acc[0] += v0.x + v1.x + v2.x + v3.x;
        acc[1] += v0.y + v1.y + v2.y + v3.y;
        acc[2] += v0.z + v1.z + v2.z + v3.z;
        acc[3] += v0.w + v1.w + v2.w + v3.w;
    }
#pragma unroll
    for (int k = 0; k < 4; k++) {
#pragma unroll
        for (int o = 16; o >= 4; o >>= 1) acc[k] += __shfl_down_sync(0xffffffffu, acc[k], o);
    }
    int lane = threadIdx.x & 31;             // lanes 0..3 hold class lane (= t0&3)
    if (lane < 4) {
#pragma unroll
        for (int k = 0; k < 4; k++) atomicAdd(&sb[lane * 4 + k], acc[k]);
    }
    __syncthreads();
    if (threadIdx.x < 16) atomicAdd(&g_est[threadIdx.x], 0.5 * (double)sb[threadIdx.x]);
}

// node transform; edge-BN affine recomputed per block from g_est (folds fin_edge)
__global__ __launch_bounds__(TPB) void node_kernel(
    const float* __restrict__ Wp, const float* __restrict__ bp,
    const float* __restrict__ egamma, const float* __restrict__ ebeta,
    long long E, int N)
{
    __shared__ float Wps[256];
    __shared__ float bps[16];
    __shared__ float eac[32];
    __shared__ float sred[32];
    if (threadIdx.x < 256) Wps[threadIdx.x] = Wp[threadIdx.x];
    if (threadIdx.x < 16)  bps[threadIdx.x] = bp[threadIdx.x];
    if (threadIdx.x < 32)  sred[threadIdx.x] = 0.0f;
    if (threadIdx.x < 16) {
        int i = threadIdx.x;
        double invE = 1.0 / (double)E;
        double mean = g_est[i] * invE;
        double var = g_est[16 + i] * invE - mean * mean;
        if (var < 0.0) var = 0.0;
        float a = egamma[i] * rsqrtf((float)var + 1e-5f);
        eac[i] = a;
        eac[16 + i] = ebeta[i] - (float)mean * a;
    }
    __syncthreads();

    int n = blockIdx.x * blockDim.x + threadIdx.x;
    float s0[16], s1[16];
#pragma unroll
    for (int i = 0; i < 16; i++) { s0[i] = 0.0f; s1[i] = 0.0f; }

    if (n < N) {
        float deg = g_deg[n];
        float invd = 1.0f / fmaxf(deg, 1.0f);
        const float4* S4 = (const float4*)&g_S[(size_t)n * 16];
        float t[16];
#pragma unroll
        for (int q = 0; q < 4; q++) {
            float4 sv = S4[q];
            t[4*q+0] = (eac[4*q+0] * sv.x + deg * eac[16 + 4*q+0]) * invd;
            t[4*q+1] = (eac[4*q+1] * sv.y + deg * eac[16 + 4*q+1]) * invd;
            t[4*q+2] = (eac[4*q+2] * sv.z + deg * eac[16 + 4*q+2]) * invd;
            t[4*q+3] = (eac[4*q+3] * sv.w + deg * eac[16 + 4*q+3]) * invd;
        }
        float u[16];
#pragma unroll
        for (int i = 0; i < 16; i++) u[i] = bps[i];
#pragma unroll
        for (int j = 0; j < 16; j++) {
#pragma unroll
            for (int i = 0; i < 16; i++) u[i] = fmaf(t[j], Wps[j * 16 + i], u[i]);
        }
        float4* U4 = (float4*)&g_u[(size_t)n * 16];
#pragma unroll
        for (int q = 0; q < 4; q++)
            U4[q] = make_float4(u[4*q], u[4*q+1], u[4*q+2], u[4*q+3]);
#pragma unroll
        for (int i = 0; i < 16; i++) {
            s0[i] = u[i];
            s1[i] = u[i] * u[i];
        }
    }

    int lane = threadIdx.x & 31;
#pragma unroll
    for (int i = 0; i < 16; i++) {
        float a = warp_sum(s0[i]);
        float b = warp_sum(s1[i]);
        if (lane == 0) {
            atomicAdd(&sred[i], a);
            atomicAdd(&sred[16 + i], b);
        }
    }
    __syncthreads();
    if (threadIdx.x < 32) atomicAdd(&g_nst[threadIdx.x], (double)sred[threadIdx.x]);
}

// final: node-BN affine recomputed per block from g_nst (folds fin_node)
__global__ void final_kernel(float* __restrict__ out,
                             const float* __restrict__ ngamma,
                             const float* __restrict__ nbeta, int N) {
    __shared__ float nac[32];
    if (threadIdx.x < 16) {
        int i = threadIdx.x;
        double invN = 1.0 / (double)N;
        double mean = g_nst[i] * invN;
        double var = g_nst[16 + i] * invN - mean * mean;
        if (var < 0.0) var = 0.0;
        float a = ngamma[i] * rsqrtf((float)var + 1e-5f);
        nac[i] = a;
        nac[16 + i] = nbeta[i] - (float)mean * a;
    }
    __syncthreads();

    int idx4 = blockIdx.x * blockDim.x + threadIdx.x;
    int tot4 = N * 4;
    if (idx4 < tot4) {
        int base = (idx4 * 4) & 15;
        const float4* u4 = (const float4*)g_u;
        float4 v = u4[idx4];
        float4 r;
        r.x = nac[base + 0] * v.x + nac[16 + base + 0];
        r.y = nac[base + 1] * v.y + nac[16 + base + 1];
        r.z = nac[base + 2] * v.z + nac[16 + base + 2];
        r.w = nac[base + 3] * v.w + nac[16 + base + 3];
        ((float4*)out)[idx4] = r;
    }
}

// ---------------- launch ----------------
extern "C" void kernel_launch(void* const* d_in, const int* in_sizes, int n_in,
                              void* d_out, int out_size)
{
    const float* coords  = (const float*)d_in[0];
    const float* normals = (const float*)d_in[1];
    const float* curv    = (const float*)d_in[2];
    const void*  eidx    = d_in[3];
    const float* W1 = (const float*)d_in[4];
    const float* b1 = (const float*)d_in[5];
    const float* W2 = (const float*)d_in[6];
    const float* b2 = (const float*)d_in[7];
    const float* W3 = (const float*)d_in[8];
    const float* b3 = (const float*)d_in[9];
    const float* bn_e_gamma = (const float*)d_in[10];
    const float* bn_e_beta  = (const float*)d_in[11];
    const float* Wp = (const float*)d_in[12];
    const float* bp = (const float*)d_in[13];
    const float* bn_n_gamma = (const float*)d_in[14];
    const float* bn_n_beta  = (const float*)d_in[15];

    int N = in_sizes[0] / 3;
    long long E = (long long)(in_sizes[3] / 2);
    float* out = (float*)d_out;

    prep_kernel<<<(N * 4 + TPB - 1) / TPB, TPB>>>(coords, normals, curv, eidx, N);
    edge_kernel<<<EGRID, ETPB>>>(eidx, E, W1, b1, W2, b2, W3, b3);
    sumS_kernel<<<592, TPB>>>(N);
    node_kernel<<<(N + TPB - 1) / TPB, TPB>>>(Wp, bp, bn_e_gamma, bn_e_beta, E, N);
    final_kernel<<<(N * 4 + TPB - 1) / TPB, TPB>>>(out, bn_n_gamma, bn_n_beta, N);
}